// round 17
// baseline (speedup 1.0000x reference)
#include <cuda_runtime.h>
#include <math.h>

#define NG  3200   // graphs = B*L
#define E   50     // nodes per graph
#define D   100    // embedding dim
#define H   100    // head dim
#define GPC 4      // graphs per CTA in fused kernel

// Scratch
__device__ __align__(16) float g_A[D * D];   // A: u[d] = sum_e x0[e]*g_A[e*D+d]
__device__ __align__(16) float g_cp[128];    // Wk @ bq (pad)
__device__ __align__(16) float g_bp[128];    // bv + bs (pad)

// ---------------------------------------------------------------------------
// K1: A = Wk Wq^T (row e per block), block 0 also c = Wk bq, bvs = bv+bs.
// ---------------------------------------------------------------------------
__global__ void k_pre(const float* __restrict__ Wq, const float* __restrict__ bq,
                      const float* __restrict__ Wk,
                      const float* __restrict__ bv, const float* __restrict__ bs) {
    int b = blockIdx.x, t = threadIdx.x;
    __shared__ __align__(16) float wk[D * 101];
    __shared__ __align__(16) float wq[H];
    __shared__ __align__(16) float bqs[H];
    if (t < H) wq[t] = Wq[b * H + t];
    if (b == 0 && t < H) bqs[t] = bq[t];
    for (int i = t; i < D * H; i += 128) {
        int r = i / H, cc = i - r * H;
        wk[r * 101 + cc] = Wk[i];
    }
    __syncthreads();
    if (t < D) {
        float acc = 0.f;
        #pragma unroll 4
        for (int h = 0; h < H; ++h) acc = fmaf(wk[t * 101 + h], wq[h], acc);
        g_A[b * D + t] = acc;
    }
    if (b == 0) {
        float c = 0.f, bb = 0.f;
        if (t < D) {
            #pragma unroll 4
            for (int h = 0; h < H; ++h) c = fmaf(wk[t * 101 + h], bqs[h], c);
            bb = bv[t] + bs[t];
        }
        g_cp[t] = c;
        g_bp[t] = bb;
    }
}

// ---------------------------------------------------------------------------
// K2 (fused): per-CTA = 4 graphs, 256 thr, grid = 800.
//  A) stream A rows coalesced, shared across 4 graphs -> u (warp partials,
//     smem reduce)
//  B) 4x sequential: gather X, scores vs u, softmax, w -> wx=[w|x0]
//  C) stream Wv/Ws rows coalesced, shared across 4 graphs -> out
// All float4-accessed smem arrays are explicitly 16B-aligned (the R14 fault).
// ---------------------------------------------------------------------------
__global__ __launch_bounds__(256) void k_fused(const int* __restrict__ nid,
                                               const int* __restrict__ adj,
                                               const float* __restrict__ emb,
                                               const float* __restrict__ Wv,
                                               const float* __restrict__ Ws,
                                               float* __restrict__ out) {
    __shared__ __align__(16) float X[E * 101];    // 20.2KB gathered rows
    __shared__ __align__(16) float red[32 * 104]; // 13.3KB warp x graph partials
    __shared__ __align__(16) float u4[GPC * 104]; // u per graph
    __shared__ __align__(16) float x04[GPC * 104];// x0 per graph
    __shared__ __align__(16) float wx4[GPC * 200];// [w | x0] per graph
    __shared__ __align__(16) float sc[E];
    __shared__ __align__(16) float ps[E];
    __shared__ __align__(16) int ids4[GPC * 52];  // compacted neighbor ids
    __shared__ int cnt4[GPC];

    int tid = threadIdx.x, warp = tid >> 5, lane = tid & 31;
    int gbase = blockIdx.x * GPC;

    // 1. ids + mask + ballot compaction: warp g handles graph g (g<4)
    if (warp < GPC) {
        int g = warp;
        const int* np = &nid[(gbase + g) * E];
        const int* ap = &adj[(gbase + g) * E * E];
        int j1 = lane + 32;
        int id0 = np[lane];
        int m0  = ap[lane * E];
        int id1 = 0, m1 = 0;
        if (j1 < E) { id1 = np[j1]; m1 = ap[j1 * E]; }
        unsigned b0 = __ballot_sync(0xffffffffu, m0 != 0);
        unsigned b1 = __ballot_sync(0xffffffffu, m1 != 0);
        if (m0) ids4[g * 52 + __popc(b0 & ((1u << lane) - 1u))] = id0;
        if (m1) ids4[g * 52 + __popc(b0) + __popc(b1 & ((1u << lane) - 1u))] = id1;
        if (lane == 0) cnt4[g] = __popc(b0) + __popc(b1);
    }
    __syncthreads();

    // 2. x0 rows (compacted row 0 == node 0, self-loop guaranteed)
    if (tid < GPC * 25) {
        int g = tid / 25, c = tid % 25;
        float4 v = reinterpret_cast<const float4*>(emb)[ids4[g * 52] * 25 + c];
        *reinterpret_cast<float4*>(&x04[g * 104 + 4 * c]) = v;
    }
    __syncthreads();

    // 3. Phase A: u partials. warp covers e = warp, warp+8, ...; lanes = cols.
    {
        float4 a0 = make_float4(0.f, 0.f, 0.f, 0.f);
        float4 a1 = a0, a2 = a0, a3 = a0;
        for (int e = warp; e < D; e += 8) {
            float4 w4 = make_float4(0.f, 0.f, 0.f, 0.f);
            if (lane < 25) w4 = *reinterpret_cast<const float4*>(&g_A[e * D + 4 * lane]);
            float xa = x04[e],           xb = x04[104 + e];
            float xc = x04[208 + e],     xd = x04[312 + e];
            a0.x = fmaf(xa, w4.x, a0.x); a0.y = fmaf(xa, w4.y, a0.y);
            a0.z = fmaf(xa, w4.z, a0.z); a0.w = fmaf(xa, w4.w, a0.w);
            a1.x = fmaf(xb, w4.x, a1.x); a1.y = fmaf(xb, w4.y, a1.y);
            a1.z = fmaf(xb, w4.z, a1.z); a1.w = fmaf(xb, w4.w, a1.w);
            a2.x = fmaf(xc, w4.x, a2.x); a2.y = fmaf(xc, w4.y, a2.y);
            a2.z = fmaf(xc, w4.z, a2.z); a2.w = fmaf(xc, w4.w, a2.w);
            a3.x = fmaf(xd, w4.x, a3.x); a3.y = fmaf(xd, w4.y, a3.y);
            a3.z = fmaf(xd, w4.z, a3.z); a3.w = fmaf(xd, w4.w, a3.w);
        }
        if (lane < 25) {
            *reinterpret_cast<float4*>(&red[(warp * 4 + 0) * 104 + 4 * lane]) = a0;
            *reinterpret_cast<float4*>(&red[(warp * 4 + 1) * 104 + 4 * lane]) = a1;
            *reinterpret_cast<float4*>(&red[(warp * 4 + 2) * 104 + 4 * lane]) = a2;
            *reinterpret_cast<float4*>(&red[(warp * 4 + 3) * 104 + 4 * lane]) = a3;
        }
    }
    __syncthreads();
    for (int t = tid; t < GPC * D; t += 256) {      // reduce u + fill wx upper
        int g = t / D, d = t - g * D;
        float s = g_cp[d];
        #pragma unroll
        for (int w2 = 0; w2 < 8; ++w2) s += red[(w2 * 4 + g) * 104 + d];
        u4[g * 104 + d] = s;
        wx4[g * 200 + D + d] = x04[g * 104 + d];
    }
    __syncthreads();

    // 4. Phase B: per-graph attention (sequential, X buffer reused)
    for (int gi = 0; gi < GPC; ++gi) {
        int cnt = cnt4[gi];
        for (int q = tid; q < cnt * 25; q += 256) {
            int r = q / 25, c = q % 25;
            float4 v = reinterpret_cast<const float4*>(emb)[ids4[gi * 52 + r] * 25 + c];
            float* dst = &X[r * 101 + 4 * c];
            dst[0] = v.x; dst[1] = v.y; dst[2] = v.z; dst[3] = v.w;
        }
        __syncthreads();
        if (tid < cnt) {
            const float* xr = &X[tid * 101];
            const float* uu = &u4[gi * 104];
            float s0 = 0.f, s1 = 0.f;
            #pragma unroll 10
            for (int d2 = 0; d2 < D; d2 += 2) {
                s0 = fmaf(xr[d2],     uu[d2],     s0);
                s1 = fmaf(xr[d2 + 1], uu[d2 + 1], s1);
            }
            sc[tid] = (s0 + s1) * 0.1f;     // /sqrt(H)
        }
        __syncthreads();
        float mx = -1e30f;
        for (int j = 0; j < cnt; ++j) mx = fmaxf(mx, sc[j]);
        if (tid < cnt) ps[tid] = __expf(sc[tid] - mx);
        __syncthreads();
        float S = 0.f;
        for (int j = 0; j < cnt; ++j) S += ps[j];
        float inv = 1.0f / S;               // self-loop -> S > 0
        if (tid < D) {
            float w = 0.f;
            for (int j = 0; j < cnt; ++j) w = fmaf(ps[j], X[j * 101 + tid], w);
            wx4[gi * 200 + tid] = w * inv;
        }
        __syncthreads();
    }

    // 5. Phase C: out partials. warp covers k = warp, warp+8, ...; lanes = cols.
    {
        float4 a0 = make_float4(0.f, 0.f, 0.f, 0.f);
        float4 a1 = a0, a2 = a0, a3 = a0;
        for (int k = 0; k < 200; k += 8) {
            int kk = k + warp;
            const float* src = (kk < D) ? &Wv[kk * H] : &Ws[(kk - D) * H];
            float4 w4 = make_float4(0.f, 0.f, 0.f, 0.f);
            if (lane < 25) w4 = *reinterpret_cast<const float4*>(&src[4 * lane]);
            float xa = wx4[kk],            xb = wx4[200 + kk];
            float xc = wx4[400 + kk],      xd = wx4[600 + kk];
            a0.x = fmaf(xa, w4.x, a0.x); a0.y = fmaf(xa, w4.y, a0.y);
            a0.z = fmaf(xa, w4.z, a0.z); a0.w = fmaf(xa, w4.w, a0.w);
            a1.x = fmaf(xb, w4.x, a1.x); a1.y = fmaf(xb, w4.y, a1.y);
            a1.z = fmaf(xb, w4.z, a1.z); a1.w = fmaf(xb, w4.w, a1.w);
            a2.x = fmaf(xc, w4.x, a2.x); a2.y = fmaf(xc, w4.y, a2.y);
            a2.z = fmaf(xc, w4.z, a2.z); a2.w = fmaf(xc, w4.w, a2.w);
            a3.x = fmaf(xd, w4.x, a3.x); a3.y = fmaf(xd, w4.y, a3.y);
            a3.z = fmaf(xd, w4.z, a3.z); a3.w = fmaf(xd, w4.w, a3.w);
        }
        if (lane < 25) {
            *reinterpret_cast<float4*>(&red[(warp * 4 + 0) * 104 + 4 * lane]) = a0;
            *reinterpret_cast<float4*>(&red[(warp * 4 + 1) * 104 + 4 * lane]) = a1;
            *reinterpret_cast<float4*>(&red[(warp * 4 + 2) * 104 + 4 * lane]) = a2;
            *reinterpret_cast<float4*>(&red[(warp * 4 + 3) * 104 + 4 * lane]) = a3;
        }
    }
    __syncthreads();
    for (int t = tid; t < GPC * H; t += 256) {
        int g = t / H, h = t - g * H;
        float s = g_bp[h];
        #pragma unroll
        for (int w2 = 0; w2 < 8; ++w2) s += red[(w2 * 4 + g) * 104 + h];
        out[(gbase + g) * H + h] = s;
    }
}

// ---------------------------------------------------------------------------
extern "C" void kernel_launch(void* const* d_in, const int* in_sizes, int n_in,
                              void* d_out, int out_size) {
    const int*   nid = (const int*)d_in[0];
    const int*   adj = (const int*)d_in[1];
    const float* emb = (const float*)d_in[2];
    const float* Wq  = (const float*)d_in[3];
    const float* bq  = (const float*)d_in[4];
    const float* Wk  = (const float*)d_in[5];
    // d_in[6] = bk: cancels in softmax (constant per-row shift)
    const float* Wv  = (const float*)d_in[7];
    const float* bv  = (const float*)d_in[8];
    const float* Ws  = (const float*)d_in[9];
    const float* bs  = (const float*)d_in[10];
    float* out = (float*)d_out;

    k_pre<<<D, 128>>>(Wq, bq, Wk, bv, bs);
    k_fused<<<NG / GPC, 256>>>(nid, adj, emb, Wv, Ws, out);
}